// round 1
// baseline (speedup 1.0000x reference)
#include <cuda_runtime.h>
#include <math.h>

// Problem constants (B=4, S=4096, D=2048, E=8, K=2)
#define NTOK    16384          // B*S tokens
#define DIM     2048
#define NEXP    8
#define TOPK    2
#define NASSIGN (NTOK*TOPK)    // 32768
#define CAP     5120           // int(NTOK*K/E * 1.25)

// Output layout (float32, concatenated reference tuple):
// [0, 32768)            expert_indices (as float)
// [32768, 65536)        expert_weights
// [65536]               load_balance_loss
// [65537, 98305)        expert_mask

// Scratch (static __device__ globals — no runtime allocation)
__device__ int   g_cnt[NEXP];
__device__ float g_probsum[NEXP];
__device__ unsigned long long g_bucket[NEXP][NASSIGN];

__global__ void zero_kernel() {
    int t = threadIdx.x;
    if (t < NEXP) { g_cnt[t] = 0; g_probsum[t] = 0.0f; }
}

// Main pass: logits GEMV + softmax + top-2 + renorm + outputs + stats.
// 256 threads = 8 warps; each warp handles 4 tokens (amortizes smem w reads 4x).
__global__ __launch_bounds__(256) void router_main(const float* __restrict__ x,
                                                   const float* __restrict__ wg,
                                                   float* __restrict__ out) {
    extern __shared__ float sw[];              // 8*2048 floats = 64 KB
    __shared__ float s_prob[NEXP];

    int tid = threadIdx.x;
    if (tid < NEXP) s_prob[tid] = 0.0f;

    // stage w_gate into shared (vectorized)
    float4* sw4 = (float4*)sw;
    const float4* wg4 = (const float4*)wg;
    #pragma unroll
    for (int i = tid; i < NEXP * DIM / 4; i += 256) sw4[i] = wg4[i];
    __syncthreads();

    const int warp = tid >> 5;
    const int lane = tid & 31;
    const int tbase = (blockIdx.x * 8 + warp) * 4;   // 4 tokens per warp

    const float4* xr0 = (const float4*)(x + (size_t)(tbase + 0) * DIM);
    const float4* xr1 = (const float4*)(x + (size_t)(tbase + 1) * DIM);
    const float4* xr2 = (const float4*)(x + (size_t)(tbase + 2) * DIM);
    const float4* xr3 = (const float4*)(x + (size_t)(tbase + 3) * DIM);

    float acc[4][NEXP];
    #pragma unroll
    for (int t = 0; t < 4; t++)
        #pragma unroll
        for (int e = 0; e < NEXP; e++) acc[t][e] = 0.0f;

    // Each lane covers 16 float4 columns (stride 32 float4 = 128B coalesced)
    #pragma unroll 2
    for (int i = 0; i < 16; i++) {
        int c = i * 32 + lane;
        float4 xv0 = xr0[c];
        float4 xv1 = xr1[c];
        float4 xv2 = xr2[c];
        float4 xv3 = xr3[c];
        #pragma unroll
        for (int e = 0; e < NEXP; e++) {
            float4 wv = sw4[e * (DIM / 4) + c];
            acc[0][e] += xv0.x * wv.x + xv0.y * wv.y + xv0.z * wv.z + xv0.w * wv.w;
            acc[1][e] += xv1.x * wv.x + xv1.y * wv.y + xv1.z * wv.z + xv1.w * wv.w;
            acc[2][e] += xv2.x * wv.x + xv2.y * wv.y + xv2.z * wv.z + xv2.w * wv.w;
            acc[3][e] += xv3.x * wv.x + xv3.y * wv.y + xv3.z * wv.z + xv3.w * wv.w;
        }
    }

    // Warp butterfly reduce: after this, every lane holds the full sums
    #pragma unroll
    for (int t = 0; t < 4; t++)
        #pragma unroll
        for (int e = 0; e < NEXP; e++) {
            float v = acc[t][e];
            v += __shfl_xor_sync(0xffffffffu, v, 16);
            v += __shfl_xor_sync(0xffffffffu, v, 8);
            v += __shfl_xor_sync(0xffffffffu, v, 4);
            v += __shfl_xor_sync(0xffffffffu, v, 2);
            v += __shfl_xor_sync(0xffffffffu, v, 1);
            acc[t][e] = v;
        }

    // Lanes 0..3: scalar epilogue for their token
    if (lane < 4) {
        int token = tbase + lane;
        float p[NEXP];
        float m = acc[lane][0];
        #pragma unroll
        for (int e = 1; e < NEXP; e++) m = fmaxf(m, acc[lane][e]);
        float s = 0.0f;
        #pragma unroll
        for (int e = 0; e < NEXP; e++) { p[e] = expf(acc[lane][e] - m); s += p[e]; }
        float inv = 1.0f / s;
        #pragma unroll
        for (int e = 0; e < NEXP; e++) p[e] *= inv;

        // top-2, ties -> lowest index (strict greater)
        int i1 = 0; float b1 = p[0];
        #pragma unroll
        for (int e = 1; e < NEXP; e++) if (p[e] > b1) { b1 = p[e]; i1 = e; }
        int i2 = -1; float b2 = -1.0f;
        #pragma unroll
        for (int e = 0; e < NEXP; e++) if (e != i1 && p[e] > b2) { b2 = p[e]; i2 = e; }

        float ssum = b1 + b2;
        float w1 = b1 / ssum, w2 = b2 / ssum;

        int n0 = token * 2;
        out[n0]     = (float)i1;
        out[n0 + 1] = (float)i2;
        out[NASSIGN + n0]     = w1;
        out[NASSIGN + n0 + 1] = w2;
        out[2 * NASSIGN + 1 + n0]     = 1.0f;   // mask default keep
        out[2 * NASSIGN + 1 + n0 + 1] = 1.0f;

        // per-expert bucket append (order-independent keys: weight desc, idx asc)
        int s1 = atomicAdd(&g_cnt[i1], 1);
        g_bucket[i1][s1] = ((unsigned long long)__float_as_uint(w1) << 32) |
                           (unsigned)(~(unsigned)n0);
        int s2 = atomicAdd(&g_cnt[i2], 1);
        g_bucket[i2][s2] = ((unsigned long long)__float_as_uint(w2) << 32) |
                           (unsigned)(~(unsigned)(n0 + 1));

        #pragma unroll
        for (int e = 0; e < NEXP; e++) atomicAdd(&s_prob[e], p[e]);
    }
    __syncthreads();
    if (tid < NEXP) atomicAdd(&g_probsum[tid], s_prob[tid]);
}

__global__ void loss_kernel(float* __restrict__ out) {
    if (threadIdx.x == 0 && blockIdx.x == 0) {
        float imp[NEXP], imps = 0.0f;
        #pragma unroll
        for (int e = 0; e < NEXP; e++) { imp[e] = g_probsum[e]; imps += imp[e]; }
        float loss = 0.0f;
        #pragma unroll
        for (int e = 0; e < NEXP; e++)
            loss += (imp[e] / imps) * ((float)g_cnt[e] / (float)NASSIGN);
        out[2 * NASSIGN] = (float)NEXP * loss;
    }
}

// Capacity drop: only runs when an expert exceeds CAP (rare at these shapes).
// rank(i) = #{j : key_j > key_i}; keep iff rank < CAP, matching
// lexsort((-w, expert)) stable ordering with flat-index tiebreak.
__global__ void drop_kernel(float* __restrict__ out) {
    int e = blockIdx.y;
    int c = g_cnt[e];
    if (c <= CAP) return;
    for (int i = blockIdx.x * blockDim.x + threadIdx.x; i < c;
         i += gridDim.x * blockDim.x) {
        unsigned long long ki = g_bucket[e][i];
        int rank = 0;
        for (int j = 0; j < c; j++) rank += (g_bucket[e][j] > ki) ? 1 : 0;
        if (rank >= CAP) {
            unsigned n = ~(unsigned)(ki & 0xffffffffull);
            out[2 * NASSIGN + 1 + n] = 0.0f;
        }
    }
}

extern "C" void kernel_launch(void* const* d_in, const int* in_sizes, int n_in,
                              void* d_out, int out_size) {
    const float* x  = (const float*)d_in[0];   // [4,4096,2048] f32
    const float* wg = (const float*)d_in[1];   // [8,2048] f32
    float* out = (float*)d_out;

    (void)in_sizes; (void)n_in; (void)out_size;

    // 64 KB dynamic smem opt-in (idempotent, capture-safe host call)
    cudaFuncSetAttribute(router_main, cudaFuncAttributeMaxDynamicSharedMemorySize,
                         NEXP * DIM * (int)sizeof(float));

    zero_kernel<<<1, 32>>>();
    router_main<<<NTOK / 32, 256, NEXP * DIM * sizeof(float)>>>(x, wg, out);
    loss_kernel<<<1, 32>>>(out);
    drop_kernel<<<dim3(8, NEXP), 256>>>(out);
}

// round 3
// speedup vs baseline: 1.2348x; 1.2348x over previous
#include <cuda_runtime.h>
#include <math.h>

// Problem constants (B=4, S=4096, D=2048, E=8, K=2)
#define NTOK    16384
#define DIM     2048
#define NEXP    8
#define NASSIGN (NTOK*2)       // 32768
#define CAP     5120           // int(NTOK*2/8 * 1.25)

// Output layout (float32): [0,32768) indices | [32768,65536) weights |
// [65536] loss | [65537,98305) mask

// Scratch: __device__ globals (zero-initialized at load; finalize resets
// counters after each use so every graph replay sees zeros).
__device__ int   g_cnt[NEXP];
__device__ float g_probsum[NEXP];
__device__ unsigned long long g_bucket[NEXP][NASSIGN];

// Packed fp32x2 FMA (Blackwell): d = a*b + d elementwise on two f32 lanes.
// NOTE: accumulator is %0 (read+write via "+l") — do NOT name a 4th operand.
__device__ __forceinline__ void ffma2(unsigned long long& d,
                                      unsigned long long a,
                                      unsigned long long b) {
    asm("fma.rn.f32x2 %0, %1, %2, %0;" : "+l"(d) : "l"(a), "l"(b));
}
__device__ __forceinline__ float unpack_sum(unsigned long long v) {
    unsigned lo, hi;
    asm("mov.b64 {%0, %1}, %2;" : "=r"(lo), "=r"(hi) : "l"(v));
    return __uint_as_float(lo) + __uint_as_float(hi);
}

// Main pass: logits GEMV + softmax + top-2 + renorm + outputs + stats.
// 256 threads = 8 warps; 4 tokens per warp; f32x2 halves = even/odd D pairs.
__global__ __launch_bounds__(256, 2)
void router_main(const float* __restrict__ x,
                 const float* __restrict__ wg,
                 float* __restrict__ out) {
    extern __shared__ float sw[];              // 8*2048 f32 = 64 KB
    __shared__ float s_prob[NEXP];

    int tid = threadIdx.x;
    if (tid < NEXP) s_prob[tid] = 0.0f;

    // stage w_gate into shared (vectorized, one-time; L2-resident after wave 1)
    float4* sw4 = (float4*)sw;
    const float4* wg4 = (const float4*)wg;
    #pragma unroll
    for (int i = tid; i < NEXP * DIM / 4; i += 256) sw4[i] = wg4[i];
    __syncthreads();

    const int warp = tid >> 5;
    const int lane = tid & 31;
    const int tbase = (blockIdx.x * 8 + warp) * 4;

    const ulonglong2* xr0 = (const ulonglong2*)(x + (size_t)(tbase + 0) * DIM);
    const ulonglong2* xr1 = (const ulonglong2*)(x + (size_t)(tbase + 1) * DIM);
    const ulonglong2* xr2 = (const ulonglong2*)(x + (size_t)(tbase + 2) * DIM);
    const ulonglong2* xr3 = (const ulonglong2*)(x + (size_t)(tbase + 3) * DIM);
    const ulonglong2* sw2 = (const ulonglong2*)sw;

    unsigned long long acc[4][NEXP];
    #pragma unroll
    for (int t = 0; t < 4; t++)
        #pragma unroll
        for (int e = 0; e < NEXP; e++) acc[t][e] = 0ull;

    // 16 chunks of 4 floats (one ull2 = float4) per lane; lanes stride 32.
    #pragma unroll 2
    for (int i = 0; i < 16; i++) {
        int c = i * 32 + lane;
        ulonglong2 x0 = xr0[c];
        ulonglong2 x1 = xr1[c];
        ulonglong2 x2 = xr2[c];
        ulonglong2 x3 = xr3[c];
        #pragma unroll
        for (int e = 0; e < NEXP; e++) {
            ulonglong2 wv = sw2[e * (DIM / 4) + c];
            ffma2(acc[0][e], x0.x, wv.x); ffma2(acc[0][e], x0.y, wv.y);
            ffma2(acc[1][e], x1.x, wv.x); ffma2(acc[1][e], x1.y, wv.y);
            ffma2(acc[2][e], x2.x, wv.x); ffma2(acc[2][e], x2.y, wv.y);
            ffma2(acc[3][e], x3.x, wv.x); ffma2(acc[3][e], x3.y, wv.y);
        }
    }

    // Collapse f32x2 halves, then warp butterfly so lanes 0-3 hold full sums.
    float logit[4][NEXP];
    #pragma unroll
    for (int t = 0; t < 4; t++)
        #pragma unroll
        for (int e = 0; e < NEXP; e++) {
            float v = unpack_sum(acc[t][e]);
            v += __shfl_xor_sync(0xffffffffu, v, 16);
            v += __shfl_xor_sync(0xffffffffu, v, 8);
            v += __shfl_xor_sync(0xffffffffu, v, 4);
            v += __shfl_xor_sync(0xffffffffu, v, 2);
            v += __shfl_xor_sync(0xffffffffu, v, 1);
            logit[t][e] = v;
        }

    if (lane < 4) {
        int token = tbase + lane;
        float p[NEXP];
        float m = logit[lane][0];
        #pragma unroll
        for (int e = 1; e < NEXP; e++) m = fmaxf(m, logit[lane][e]);
        float s = 0.0f;
        #pragma unroll
        for (int e = 0; e < NEXP; e++) { p[e] = expf(logit[lane][e] - m); s += p[e]; }
        float inv = 1.0f / s;
        #pragma unroll
        for (int e = 0; e < NEXP; e++) p[e] *= inv;

        // top-2, ties -> lowest index
        int i1 = 0; float b1 = p[0];
        #pragma unroll
        for (int e = 1; e < NEXP; e++) if (p[e] > b1) { b1 = p[e]; i1 = e; }
        int i2 = -1; float b2 = -1.0f;
        #pragma unroll
        for (int e = 0; e < NEXP; e++) if (e != i1 && p[e] > b2) { b2 = p[e]; i2 = e; }

        float ssum = b1 + b2;
        float w1 = b1 / ssum, w2 = b2 / ssum;

        int n0 = token * 2;
        out[n0]     = (float)i1;
        out[n0 + 1] = (float)i2;
        out[NASSIGN + n0]     = w1;
        out[NASSIGN + n0 + 1] = w2;
        out[2 * NASSIGN + 1 + n0]     = 1.0f;
        out[2 * NASSIGN + 1 + n0 + 1] = 1.0f;

        // per-expert bucket append; key = (weight desc, flat idx asc)
        int s1 = atomicAdd(&g_cnt[i1], 1);
        g_bucket[i1][s1] = ((unsigned long long)__float_as_uint(w1) << 32) |
                           (unsigned)(~(unsigned)n0);
        int s2 = atomicAdd(&g_cnt[i2], 1);
        g_bucket[i2][s2] = ((unsigned long long)__float_as_uint(w2) << 32) |
                           (unsigned)(~(unsigned)(n0 + 1));

        #pragma unroll
        for (int e = 0; e < NEXP; e++) atomicAdd(&s_prob[e], p[e]);
    }
    __syncthreads();
    if (tid < NEXP) atomicAdd(&g_probsum[tid], s_prob[tid]);
}

// Single epilogue block: load-balance loss + (rare) capacity drop + reset
// the global counters so the next graph replay starts from zero.
__global__ void finalize_kernel(float* __restrict__ out) {
    __shared__ int cnt[NEXP];
    int tid = threadIdx.x;
    if (tid < NEXP) cnt[tid] = g_cnt[tid];
    __syncthreads();

    if (tid == 0) {
        float imp[NEXP], imps = 0.0f;
        #pragma unroll
        for (int e = 0; e < NEXP; e++) { imp[e] = g_probsum[e]; imps += imp[e]; }
        float loss = 0.0f;
        #pragma unroll
        for (int e = 0; e < NEXP; e++)
            loss += (imp[e] / imps) * ((float)cnt[e] / (float)NASSIGN);
        out[2 * NASSIGN] = (float)NEXP * loss;
    }

    // Capacity drop: rank = #{j: key_j > key_i}; keep iff rank < CAP.
    // Matches lexsort((-w, expert)) with flat-index tiebreak. Almost never
    // triggers at these shapes (expected per-expert count ~4096 << 5120).
    for (int e = 0; e < NEXP; e++) {
        int c = cnt[e];
        if (c <= CAP) continue;
        for (int i = tid; i < c; i += blockDim.x) {
            unsigned long long ki = g_bucket[e][i];
            int rank = 0;
            for (int j = 0; j < c; j++) rank += (g_bucket[e][j] > ki) ? 1 : 0;
            if (rank >= CAP) {
                unsigned n = ~(unsigned)(ki & 0xffffffffull);
                out[2 * NASSIGN + 1 + n] = 0.0f;
            }
        }
    }
    __syncthreads();
    if (tid < NEXP) { g_cnt[tid] = 0; g_probsum[tid] = 0.0f; }
}

extern "C" void kernel_launch(void* const* d_in, const int* in_sizes, int n_in,
                              void* d_out, int out_size) {
    const float* x  = (const float*)d_in[0];
    const float* wg = (const float*)d_in[1];
    float* out = (float*)d_out;
    (void)in_sizes; (void)n_in; (void)out_size;

    cudaFuncSetAttribute(router_main, cudaFuncAttributeMaxDynamicSharedMemorySize,
                         NEXP * DIM * (int)sizeof(float));

    router_main<<<NTOK / 32, 256, NEXP * DIM * sizeof(float)>>>(x, wg, out);
    finalize_kernel<<<1, 256>>>(out);
}